// round 4
// baseline (speedup 1.0000x reference)
#include <cuda_runtime.h>
#include <math.h>

#define TT 512
#define BB 64
#define II 512
#define HH 512
#define G4 2048
#define NCTA 128
#define A_STRIDE 516          // floats; 2064B row stride ≡ 16 (mod 128) -> conflict-free float4
#define SPAD 18

typedef unsigned long long ull;

// ---------------- scratch ----------------------------------------------------
__device__ float g_xw[(size_t)TT * BB * G4];       // x@W + b
__device__ float g_a2[2][NCTA * 256];              // slice-contiguous hidden state
__device__ unsigned int g_flag[NCTA];              // monotonic publish counters

// ---------------- f32x2 helpers ----------------------------------------------
#define FMA2(d, a, b, c) \
    asm("fma.rn.f32x2 %0, %1, %2, %3;" : "=l"(d) : "l"(a), "l"(b), "l"(c))
#define ADD2(d, a, b) \
    asm("add.rn.f32x2 %0, %1, %2;" : "=l"(d) : "l"(a), "l"(b))

__device__ __forceinline__ ull packf2(float lo, float hi) {
    return (ull)__float_as_uint(lo) | ((ull)__float_as_uint(hi) << 32);
}
__device__ __forceinline__ float sum2(ull v) {
    return __uint_as_float((unsigned)v) + __uint_as_float((unsigned)(v >> 32));
}

// ---------------- sync / async-copy primitives --------------------------------
__device__ __forceinline__ void st_release_gpu(unsigned int* p, unsigned int v) {
    asm volatile("st.release.gpu.global.u32 [%0], %1;" :: "l"(p), "r"(v) : "memory");
}
__device__ __forceinline__ unsigned int ld_acquire_gpu(const unsigned int* p) {
    unsigned int v;
    asm volatile("ld.acquire.gpu.global.u32 %0, [%1];" : "=r"(v) : "l"(p) : "memory");
    return v;
}
__device__ __forceinline__ void cp_async16(void* smem_dst, const void* gsrc) {
    unsigned int d = (unsigned int)__cvta_generic_to_shared(smem_dst);
    asm volatile("cp.async.cg.shared.global [%0], [%1], 16;" :: "r"(d), "l"(gsrc));
}
#define CP_COMMIT() asm volatile("cp.async.commit_group;" ::: "memory")
#define CP_WAIT0()  asm volatile("cp.async.wait_group 0;"  ::: "memory")

// ---------------- phase 1: xW = x@W + b (unchanged from R2) -------------------
__global__ void __launch_bounds__(256, 1) xw_gemm_kernel(
    const float* __restrict__ X,
    const float* __restrict__ W,
    const float* __restrict__ bias)
{
    __shared__ ull As2[4 * 128];
    __shared__ ull Bs2[4 * 128];

    const int tid = threadIdx.x;
    const int m0 = blockIdx.y * 128;
    const int n0 = blockIdx.x * 128;
    const int ty = tid >> 4;
    const int tx = tid & 15;

    const int ar = tid >> 1;
    const int ac = (tid & 1) * 4;
    const int br = tid >> 5;
    const int bc = (tid & 31) * 4;

    ull acc[8][8];
#pragma unroll
    for (int i = 0; i < 8; i++)
#pragma unroll
        for (int j = 0; j < 8; j++) acc[i][j] = 0ull;

    for (int k0 = 0; k0 < II; k0 += 8) {
        float4 av = *(const float4*)&X[(size_t)(m0 + ar) * II + k0 + ac];
        float4 wv = *(const float4*)&W[(size_t)(k0 + br) * G4 + n0 + bc];

        As2[(ac >> 1) * 128 + ar]       = packf2(av.x, av.y);
        As2[((ac >> 1) + 1) * 128 + ar] = packf2(av.z, av.w);
        {
            float* Bsf = (float*)Bs2;
            int base = ((br >> 1) * 128 + bc) * 2 + (br & 1);
#pragma unroll
            for (int j = 0; j < 4; j++) Bsf[base + j * 2] = ((const float*)&wv)[j];
        }
        __syncthreads();

#pragma unroll
        for (int kk = 0; kk < 4; kk++) {
            ull ra[8], rb[8];
            const ulonglong2* ap = (const ulonglong2*)&As2[kk * 128 + ty * 8];
            const ulonglong2* bp = (const ulonglong2*)&Bs2[kk * 128 + tx * 8];
#pragma unroll
            for (int i = 0; i < 4; i++) { ulonglong2 v = ap[i]; ra[2*i] = v.x; ra[2*i+1] = v.y; }
#pragma unroll
            for (int j = 0; j < 4; j++) { ulonglong2 v = bp[j]; rb[2*j] = v.x; rb[2*j+1] = v.y; }
#pragma unroll
            for (int i = 0; i < 8; i++)
#pragma unroll
                for (int j = 0; j < 8; j++) FMA2(acc[i][j], ra[i], rb[j], acc[i][j]);
        }
        __syncthreads();
    }

    float bv[8];
#pragma unroll
    for (int j = 0; j < 8; j++) bv[j] = bias[n0 + tx * 8 + j];

#pragma unroll
    for (int i = 0; i < 8; i++) {
        float* orow = &g_xw[(size_t)(m0 + ty * 8 + i) * G4 + n0 + tx * 8];
#pragma unroll
        for (int j = 0; j < 8; j++) orow[j] = sum2(acc[i][j]) + bv[j];
    }
}

// ---------------- phase 2: persistent recurrence, flag-synced -----------------
__device__ __forceinline__ float sigmoidf_(float x) { return 1.0f / (1.0f + expf(-x)); }

extern __shared__ float dyn_smem[];

// smem: a_sh [64][A_STRIDE] | Up [256 kpairs][16 cols] ull | part [4][64][SPAD] ull
__global__ void __launch_bounds__(256) rnn_kernel(
    const float* __restrict__ a0,
    const float* __restrict__ U,
    float* __restrict__ out)
{
    float* a_sh = dyn_smem;
    ull*   Up   = (ull*)(dyn_smem + BB * A_STRIDE);
    ull*   part = Up + 256 * 16;

    const int tid  = threadIdx.x;
    const int cta  = blockIdx.x;
    const int hc0  = cta * 4;
    const int wid  = tid >> 5;
    const int lane = tid & 31;

    // compute-phase mapping
    const int bhalf = wid & 1;
    const int ksec  = wid >> 1;
    const int bW    = bhalf * 32 + lane;

    // activation-phase mapping
    const int bA = tid >> 2;
    const int hc = tid & 3;
    const int colA = hc0 + hc;

    // paired U slice: Up[kk*16+cc] = (U[2kk][gcol], U[2kk+1][gcol])
    for (int idx = tid; idx < 256 * 16; idx += 256) {
        int kk = idx >> 4, cc = idx & 15;
        int gcol = (cc >> 2) * HH + hc0 + (cc & 3);
        float lo = U[(size_t)(2 * kk) * G4 + gcol];
        float hi = U[(size_t)(2 * kk + 1) * G4 + gcol];
        Up[idx] = packf2(lo, hi);
    }

    // monotonic flag base (all flags equal at launch entry)
    const unsigned int base = ld_acquire_gpu(&g_flag[cta]);

    // publish a_{-1} = a0 slice into buf 1
    g_a2[1][cta * 256 + bA * 4 + hc] = a0[bA * HH + hc0 + hc];
    __syncthreads();
    if (tid == 0) st_release_gpu(&g_flag[cta], base + 1);

    for (int t = 0; t < TT; ++t) {
        const unsigned int target = base + (unsigned)t + 1;   // a_{t-1} published
        const int sbuf = (t + 1) & 1;

        // per-warp: wait for my 16 producers, then async-stage their slices
        if (lane < 16) {
            const unsigned int* fp = &g_flag[wid * 16 + lane];
            while ((int)(ld_acquire_gpu(fp) - target) < 0) { }
        }
        __syncwarp();

        const float* srcbase = g_a2[sbuf];
#pragma unroll
        for (int i = 0; i < 16; i++) {
            int p = wid * 16 + i;
#pragma unroll
            for (int r = 0; r < 2; r++) {
                int b = r * 32 + lane;
                cp_async16(&a_sh[b * A_STRIDE + p * 4],
                           &srcbase[p * 256 + b * 4]);
            }
        }
        CP_COMMIT();

        // prefetch xW gate values while copies fly
        const float* xwrow = &g_xw[((size_t)t * BB + bA) * G4 + colA];
        float xg0 = xwrow[0 * HH];
        float xg1 = xwrow[1 * HH];
        float xg2 = xwrow[2 * HH];
        float xg3 = xwrow[3 * HH];

        CP_WAIT0();
        __syncthreads();

        // partial dot products: 16 gate-cols, k in [ksec*128, ksec*128+128)
        ull acc[16];
#pragma unroll
        for (int c = 0; c < 16; c++) acc[c] = 0ull;

        const float* ar = &a_sh[bW * A_STRIDE + ksec * 128];
        const ull*   ub = &Up[(ksec * 64) * 16];

#pragma unroll 2
        for (int kk = 0; kk < 64; kk += 2) {
            ulonglong2 av = *(const ulonglong2*)&ar[kk * 2];
            const ulonglong2* u0 = (const ulonglong2*)&ub[kk * 16];
            const ulonglong2* u1 = (const ulonglong2*)&ub[(kk + 1) * 16];
#pragma unroll
            for (int c = 0; c < 8; c++) {
                ulonglong2 uv = u0[c];
                FMA2(acc[2 * c],     av.x, uv.x, acc[2 * c]);
                FMA2(acc[2 * c + 1], av.x, uv.y, acc[2 * c + 1]);
            }
#pragma unroll
            for (int c = 0; c < 8; c++) {
                ulonglong2 uv = u1[c];
                FMA2(acc[2 * c],     av.y, uv.x, acc[2 * c]);
                FMA2(acc[2 * c + 1], av.y, uv.y, acc[2 * c + 1]);
            }
        }

        {
            ull* p = &part[(ksec * 64 + bW) * SPAD];
#pragma unroll
            for (int c = 0; c < 16; c += 2)
                *(ulonglong2*)&p[c] = make_ulonglong2(acc[c], acc[c + 1]);
        }
        __syncthreads();

        // reduce + activations
        float gsum[4];
#pragma unroll
        for (int g = 0; g < 4; g++) {
            int cc = g * 4 + hc;
            ull v0 = part[(0 * 64 + bA) * SPAD + cc];
            ull v1 = part[(1 * 64 + bA) * SPAD + cc];
            ull v2 = part[(2 * 64 + bA) * SPAD + cc];
            ull v3 = part[(3 * 64 + bA) * SPAD + cc];
            ull s01, s23, s;
            ADD2(s01, v0, v1);
            ADD2(s23, v2, v3);
            ADD2(s, s01, s23);
            gsum[g] = sum2(s);
        }

        float gu   = sigmoidf_(gsum[0] + xg0);
        float gf   = sigmoidf_(gsum[1] + xg1);
        float go   = sigmoidf_(gsum[2] + xg2);
        float cand = tanhf(gsum[3] + xg3);
        float aprev = a_sh[bA * A_STRIDE + colA];
        float c_t   = gu * cand + gf * aprev;
        float a_t   = go * tanhf(c_t);

        // publish slice, then flag, then (off critical path) the output row
        g_a2[t & 1][cta * 256 + bA * 4 + hc] = a_t;
        __syncthreads();
        if (tid == 0) st_release_gpu(&g_flag[cta], base + (unsigned)t + 2);

        out[((size_t)t * BB + bA) * HH + colA] = a_t;
    }
}

// ---------------- launch ------------------------------------------------------
extern "C" void kernel_launch(void* const* d_in, const int* in_sizes, int n_in,
                              void* d_out, int out_size)
{
    const float* x  = (const float*)d_in[0];
    const float* a0 = (const float*)d_in[1];
    const float* W  = (const float*)d_in[2];
    const float* U  = (const float*)d_in[3];
    const float* bb = (const float*)d_in[4];
    float* out = (float*)d_out;

    dim3 g1(G4 / 128, (TT * BB) / 128);
    xw_gemm_kernel<<<g1, 256>>>(x, W, bb);

    const int smem_bytes = BB * A_STRIDE * 4
                         + 256 * 16 * 8
                         + 4 * 64 * SPAD * 8;
    cudaFuncSetAttribute(rnn_kernel, cudaFuncAttributeMaxDynamicSharedMemorySize, smem_bytes);
    rnn_kernel<<<NCTA, 256, smem_bytes>>>(a0, U, out);
}

// round 5
// speedup vs baseline: 1.0757x; 1.0757x over previous
#include <cuda_runtime.h>
#include <math.h>

#define TT 512
#define BB 64
#define II 512
#define HH 512
#define G4 2048
#define NCTA 128
#define CPG 64          // CTAs per group
#define BPG 32          // batches per group
#define HPC 8           // h-cols per CTA
#define NCC 32          // gate-cols per CTA (4 gates x 8 h)
#define PROW 36         // padded partial row (floats) -> conflict-free STS.128

typedef unsigned long long ull;

// ---------------- scratch ----------------------------------------------------
__device__ float g_xw[(size_t)TT * BB * G4];             // x@W + b
__device__ float g_a4[4][2][CPG][BPG * HPC];             // 4-deep slab ring
__device__ unsigned int g_flagM[NCTA];                   // monotonic per-CTA flags

// ---------------- f32x2 helpers ----------------------------------------------
#define FMA2(d, a, b, c) \
    asm("fma.rn.f32x2 %0, %1, %2, %3;" : "=l"(d) : "l"(a), "l"(b), "l"(c))

__device__ __forceinline__ ull packf2(float lo, float hi) {
    return (ull)__float_as_uint(lo) | ((ull)__float_as_uint(hi) << 32);
}
__device__ __forceinline__ float sum2(ull v) {
    return __uint_as_float((unsigned)v) + __uint_as_float((unsigned)(v >> 32));
}

__device__ __forceinline__ void st_release_gpu(unsigned int* p, unsigned int v) {
    asm volatile("st.release.gpu.global.u32 [%0], %1;" :: "l"(p), "r"(v) : "memory");
}
__device__ __forceinline__ unsigned int ld_acquire_gpu(const unsigned int* p) {
    unsigned int v;
    asm volatile("ld.acquire.gpu.global.u32 %0, [%1];" : "=r"(v) : "l"(p) : "memory");
    return v;
}

// ---------------- phase 1: xW = x@W + b (R2 kernel, known good) ---------------
__global__ void __launch_bounds__(256, 1) xw_gemm_kernel(
    const float* __restrict__ X,
    const float* __restrict__ W,
    const float* __restrict__ bias)
{
    __shared__ ull As2[4 * 128];
    __shared__ ull Bs2[4 * 128];

    const int tid = threadIdx.x;
    const int m0 = blockIdx.y * 128;
    const int n0 = blockIdx.x * 128;
    const int ty = tid >> 4;
    const int tx = tid & 15;

    const int ar = tid >> 1;
    const int ac = (tid & 1) * 4;
    const int br = tid >> 5;
    const int bc = (tid & 31) * 4;

    ull acc[8][8];
#pragma unroll
    for (int i = 0; i < 8; i++)
#pragma unroll
        for (int j = 0; j < 8; j++) acc[i][j] = 0ull;

    for (int k0 = 0; k0 < II; k0 += 8) {
        float4 av = *(const float4*)&X[(size_t)(m0 + ar) * II + k0 + ac];
        float4 wv = *(const float4*)&W[(size_t)(k0 + br) * G4 + n0 + bc];

        As2[(ac >> 1) * 128 + ar]       = packf2(av.x, av.y);
        As2[((ac >> 1) + 1) * 128 + ar] = packf2(av.z, av.w);
        {
            float* Bsf = (float*)Bs2;
            int base = ((br >> 1) * 128 + bc) * 2 + (br & 1);
#pragma unroll
            for (int j = 0; j < 4; j++) Bsf[base + j * 2] = ((const float*)&wv)[j];
        }
        __syncthreads();

#pragma unroll
        for (int kk = 0; kk < 4; kk++) {
            ull ra[8], rb[8];
            const ulonglong2* ap = (const ulonglong2*)&As2[kk * 128 + ty * 8];
            const ulonglong2* bp = (const ulonglong2*)&Bs2[kk * 128 + tx * 8];
#pragma unroll
            for (int i = 0; i < 4; i++) { ulonglong2 v = ap[i]; ra[2*i] = v.x; ra[2*i+1] = v.y; }
#pragma unroll
            for (int j = 0; j < 4; j++) { ulonglong2 v = bp[j]; rb[2*j] = v.x; rb[2*j+1] = v.y; }
#pragma unroll
            for (int i = 0; i < 8; i++)
#pragma unroll
                for (int j = 0; j < 8; j++) FMA2(acc[i][j], ra[i], rb[j], acc[i][j]);
        }
        __syncthreads();
    }

    float bv[8];
#pragma unroll
    for (int j = 0; j < 8; j++) bv[j] = bias[n0 + tx * 8 + j];

#pragma unroll
    for (int i = 0; i < 8; i++) {
        float* orow = &g_xw[(size_t)(m0 + ty * 8 + i) * G4 + n0 + tx * 8];
#pragma unroll
        for (int j = 0; j < 8; j++) orow[j] = sum2(acc[i][j]) + bv[j];
    }
}

// ---------------- phase 2: batch-grouped dataflow recurrence ------------------
__device__ __forceinline__ float sigmoidf_(float x) { return 1.0f / (1.0f + expf(-x)); }

extern __shared__ float dyn_smem[];

// smem: Up [256 kk][32 cc] ull (64KB) | part [8 ks][32 b][PROW] float (36KB)
__global__ void __launch_bounds__(256) rnn_kernel(
    const float* __restrict__ a0,
    const float* __restrict__ U,
    float* __restrict__ out)
{
    ull*   Up   = (ull*)dyn_smem;
    float* part = (float*)(Up + 256 * NCC);

    const int tid  = threadIdx.x;
    const int cta  = blockIdx.x;
    const int grp  = cta >> 6;           // 0..1
    const int p    = cta & 63;           // producer index in group
    const int hc0  = p * HPC;            // h-col base
    const int w    = tid >> 5;           // warp = ksec 0..7
    const int lane = tid & 31;           // lane = batch within group

    // activation mapping
    const int bA = tid >> 3;             // 0..31 batch in group
    const int hA = tid & 7;              // 0..7 h within CTA
    const int bG = grp * BPG + bA;       // global batch
    const int hG = hc0 + hA;             // global h col

    // Build paired-U slice: Up[kk*32+cc] = (U[2kk][gcol], U[2kk+1][gcol])
    // cc = gate*8 + hh, gcol = gate*HH + hc0 + hh
    for (int idx = tid; idx < 256 * NCC; idx += 256) {
        int kk = idx >> 5, cc = idx & 31;
        int gcol = (cc >> 3) * HH + hc0 + (cc & 7);
        Up[idx] = packf2(U[(size_t)(2 * kk) * G4 + gcol],
                         U[(size_t)(2 * kk + 1) * G4 + gcol]);
    }

    // flag epoch base (all flags equal at kernel entry)
    const unsigned int base = ld_acquire_gpu(&g_flagM[cta]);

    // publish a_{-1} = a0 slab into ring slot 3; keep aprev in register
    float aprev = a0[(size_t)bG * HH + hG];
    g_a4[3][grp][p][bA * HPC + hA] = aprev;
    __syncthreads();
    if (tid == 0) st_release_gpu(&g_flagM[cta], base + 1);

    const unsigned int* myflags = &g_flagM[grp * 64 + w * 8];

    for (int t = 0; t < TT; ++t) {
        const int rb = (t + 3) & 3;      // ring slot holding a_{t-1}
        const int wbuf = t & 3;          // ring slot for a_t
        const unsigned int target = base + (unsigned)t + 1;

        // warp w depends on producers [w*8, w*8+8): poll their flags
        if (lane < 8) {
            const unsigned int* fp = &myflags[lane];
            while ((int)(ld_acquire_gpu(fp) - target) < 0) { }
        }
        __syncwarp();

        // prefetch xW gate values for the activation phase (DRAM, long latency)
        const float* xwrow = &g_xw[((size_t)t * BB + bG) * G4 + hG];
        float xg0 = xwrow[0 * HH];
        float xg1 = xwrow[1 * HH];
        float xg2 = xwrow[2 * HH];
        float xg3 = xwrow[3 * HH];

        // stream 8 slabs: a data global->regs (.cg), U broadcast from smem
        ull acc[NCC];
#pragma unroll
        for (int c = 0; c < NCC; c++) acc[c] = 0ull;

        const float* abase = &g_a4[rb][grp][0][0];   // 64 slabs x 256 floats
        const float* s0 = abase + (w * 8) * (BPG * HPC) + lane * 8;
        float4 c0 = __ldcg((const float4*)s0);
        float4 c1 = __ldcg((const float4*)(s0 + 4));

#pragma unroll
        for (int i = 0; i < 8; i++) {
            float4 n0, n1;
            if (i < 7) {
                const float* sn = abase + (w * 8 + i + 1) * (BPG * HPC) + lane * 8;
                n0 = __ldcg((const float4*)sn);
                n1 = __ldcg((const float4*)(sn + 4));
            }
            ull av[4];
            av[0] = packf2(c0.x, c0.y);
            av[1] = packf2(c0.z, c0.w);
            av[2] = packf2(c1.x, c1.y);
            av[3] = packf2(c1.z, c1.w);
#pragma unroll
            for (int j = 0; j < 4; j++) {
                const ulonglong2* ub =
                    (const ulonglong2*)&Up[((w * 8 + i) * 4 + j) * NCC];
#pragma unroll
                for (int c = 0; c < 16; c++) {
                    ulonglong2 uv = ub[c];
                    FMA2(acc[2 * c],     av[j], uv.x, acc[2 * c]);
                    FMA2(acc[2 * c + 1], av[j], uv.y, acc[2 * c + 1]);
                }
            }
            c0 = n0; c1 = n1;
        }

        // store partials: part[(w*32+lane)*PROW + cc] (conflict-free float4)
        {
            float* pr = &part[(w * 32 + lane) * PROW];
#pragma unroll
            for (int c = 0; c < NCC; c += 4) {
                float4 v;
                v.x = sum2(acc[c + 0]);
                v.y = sum2(acc[c + 1]);
                v.z = sum2(acc[c + 2]);
                v.w = sum2(acc[c + 3]);
                *(float4*)&pr[c] = v;
            }
        }
        __syncthreads();

        // reduce over 8 ksec + activations; thread = (bA, hA)
        float gsum[4];
#pragma unroll
        for (int g = 0; g < 4; g++) {
            int cc = g * 8 + hA;
            float s = 0.f;
#pragma unroll
            for (int ks = 0; ks < 8; ks++)
                s += part[(ks * 32 + bA) * PROW + cc];
            gsum[g] = s;
        }

        float gu   = sigmoidf_(gsum[0] + xg0);
        float gf   = sigmoidf_(gsum[1] + xg1);
        float go   = sigmoidf_(gsum[2] + xg2);
        float cand = tanhf(gsum[3] + xg3);
        float c_t  = gu * cand + gf * aprev;
        float a_t  = go * tanhf(c_t);
        aprev = a_t;

        // publish slab (contiguous 1KB, coalesced), then flag, then output
        g_a4[wbuf][grp][p][bA * HPC + hA] = a_t;
        __syncthreads();
        if (tid == 0) st_release_gpu(&g_flagM[cta], base + (unsigned)t + 2);

        out[((size_t)t * BB + bG) * HH + hG] = a_t;
    }
}

// ---------------- launch ------------------------------------------------------
extern "C" void kernel_launch(void* const* d_in, const int* in_sizes, int n_in,
                              void* d_out, int out_size)
{
    const float* x  = (const float*)d_in[0];
    const float* a0 = (const float*)d_in[1];
    const float* W  = (const float*)d_in[2];
    const float* U  = (const float*)d_in[3];
    const float* bb = (const float*)d_in[4];
    float* out = (float*)d_out;

    dim3 g1(G4 / 128, (TT * BB) / 128);
    xw_gemm_kernel<<<g1, 256>>>(x, W, bb);

    const int smem_bytes = 256 * NCC * 8            // Up (64KB)
                         + 8 * 32 * PROW * 4;       // partials (36KB)
    cudaFuncSetAttribute(rnn_kernel, cudaFuncAttributeMaxDynamicSharedMemorySize, smem_bytes);
    rnn_kernel<<<NCTA, 256, smem_bytes>>>(a0, U, out);
}

// round 6
// speedup vs baseline: 1.7814x; 1.6560x over previous
#include <cuda_runtime.h>
#include <math.h>

#define TT 512
#define BB 64
#define II 512
#define HH 512
#define G4 2048
#define NCTA 128
#define CPG 64          // CTAs per group
#define BPG 32          // batches per group
#define HPC 8           // h-cols per CTA
#define NCC 32          // gate-cols per CTA (4 gates x 8 h)
#define PROW 36         // padded partial row (floats)

typedef unsigned long long ull;

// ---------------- scratch ----------------------------------------------------
__device__ float g_xw[(size_t)TT * BB * G4];             // x@W + b
__device__ float g_a4[4][2][CPG][BPG * HPC];             // 4-deep slab ring
__device__ unsigned int g_flagP[NCTA][32];               // 128B-padded flags

// ---------------- f32x2 helpers ----------------------------------------------
#define FMA2(d, a, b, c) \
    asm("fma.rn.f32x2 %0, %1, %2, %3;" : "=l"(d) : "l"(a), "l"(b), "l"(c))

__device__ __forceinline__ ull packf2(float lo, float hi) {
    return (ull)__float_as_uint(lo) | ((ull)__float_as_uint(hi) << 32);
}
__device__ __forceinline__ float sum2(ull v) {
    return __uint_as_float((unsigned)v) + __uint_as_float((unsigned)(v >> 32));
}

__device__ __forceinline__ void st_release_gpu(unsigned int* p, unsigned int v) {
    asm volatile("st.release.gpu.global.u32 [%0], %1;" :: "l"(p), "r"(v) : "memory");
}
__device__ __forceinline__ unsigned int ld_acquire_gpu(const unsigned int* p) {
    unsigned int v;
    asm volatile("ld.acquire.gpu.global.u32 %0, [%1];" : "=r"(v) : "l"(p) : "memory");
    return v;
}
__device__ __forceinline__ void wait_flag(const unsigned int* p, unsigned int target) {
    if ((int)(ld_acquire_gpu(p) - target) >= 0) return;
    while ((int)(ld_acquire_gpu(p) - target) < 0) { __nanosleep(40); }
}

// ---------------- phase 1: xW = x@W + b (R2 kernel, known good) ---------------
__global__ void __launch_bounds__(256, 1) xw_gemm_kernel(
    const float* __restrict__ X,
    const float* __restrict__ W,
    const float* __restrict__ bias)
{
    __shared__ ull As2[4 * 128];
    __shared__ ull Bs2[4 * 128];

    const int tid = threadIdx.x;
    const int m0 = blockIdx.y * 128;
    const int n0 = blockIdx.x * 128;
    const int ty = tid >> 4;
    const int tx = tid & 15;

    const int ar = tid >> 1;
    const int ac = (tid & 1) * 4;
    const int br = tid >> 5;
    const int bc = (tid & 31) * 4;

    ull acc[8][8];
#pragma unroll
    for (int i = 0; i < 8; i++)
#pragma unroll
        for (int j = 0; j < 8; j++) acc[i][j] = 0ull;

    for (int k0 = 0; k0 < II; k0 += 8) {
        float4 av = *(const float4*)&X[(size_t)(m0 + ar) * II + k0 + ac];
        float4 wv = *(const float4*)&W[(size_t)(k0 + br) * G4 + n0 + bc];

        As2[(ac >> 1) * 128 + ar]       = packf2(av.x, av.y);
        As2[((ac >> 1) + 1) * 128 + ar] = packf2(av.z, av.w);
        {
            float* Bsf = (float*)Bs2;
            int base = ((br >> 1) * 128 + bc) * 2 + (br & 1);
#pragma unroll
            for (int j = 0; j < 4; j++) Bsf[base + j * 2] = ((const float*)&wv)[j];
        }
        __syncthreads();

#pragma unroll
        for (int kk = 0; kk < 4; kk++) {
            ull ra[8], rb[8];
            const ulonglong2* ap = (const ulonglong2*)&As2[kk * 128 + ty * 8];
            const ulonglong2* bp = (const ulonglong2*)&Bs2[kk * 128 + tx * 8];
#pragma unroll
            for (int i = 0; i < 4; i++) { ulonglong2 v = ap[i]; ra[2*i] = v.x; ra[2*i+1] = v.y; }
#pragma unroll
            for (int j = 0; j < 4; j++) { ulonglong2 v = bp[j]; rb[2*j] = v.x; rb[2*j+1] = v.y; }
#pragma unroll
            for (int i = 0; i < 8; i++)
#pragma unroll
                for (int j = 0; j < 8; j++) FMA2(acc[i][j], ra[i], rb[j], acc[i][j]);
        }
        __syncthreads();
    }

    float bv[8];
#pragma unroll
    for (int j = 0; j < 8; j++) bv[j] = bias[n0 + tx * 8 + j];

#pragma unroll
    for (int i = 0; i < 8; i++) {
        float* orow = &g_xw[(size_t)(m0 + ty * 8 + i) * G4 + n0 + tx * 8];
#pragma unroll
        for (int j = 0; j < 8; j++) orow[j] = sum2(acc[i][j]) + bv[j];
    }
}

// ---------------- phase 2: recurrence, padded flags + direct ldcg -------------
__device__ __forceinline__ float sigmoidf_(float x) { return 1.0f / (1.0f + expf(-x)); }

extern __shared__ float dyn_smem[];

// smem: Up [256 kk][32 cc] ull (64KB) | part [8 ks][32 b][PROW] float (36KB)
__global__ void __launch_bounds__(256) rnn_kernel(
    const float* __restrict__ a0,
    const float* __restrict__ U,
    float* __restrict__ out)
{
    ull*   Up   = (ull*)dyn_smem;
    float* part = (float*)(Up + 256 * NCC);

    const int tid  = threadIdx.x;
    const int cta  = blockIdx.x;
    const int grp  = cta >> 6;           // 0..1
    const int p    = cta & 63;           // producer index in group
    const int hc0  = p * HPC;
    const int w    = tid >> 5;           // warp = ksec 0..7
    const int lane = tid & 31;

    // activation mapping
    const int bA = tid >> 3;             // 0..31 batch in group
    const int hA = tid & 7;              // 0..7
    const int bG = grp * BPG + bA;
    const int hG = hc0 + hA;

    // paired-U slice: Up[kk*32+cc] = (U[2kk][gcol], U[2kk+1][gcol])
    for (int idx = tid; idx < 256 * NCC; idx += 256) {
        int kk = idx >> 5, cc = idx & 31;
        int gcol = (cc >> 3) * HH + hc0 + (cc & 7);
        Up[idx] = packf2(U[(size_t)(2 * kk) * G4 + gcol],
                         U[(size_t)(2 * kk + 1) * G4 + gcol]);
    }

    const unsigned int base = ld_acquire_gpu(&g_flagP[cta][0]);

    // publish a_{-1} = a0 slab into ring slot 3; keep aprev in register
    float aprev = a0[(size_t)bG * HH + hG];
    g_a4[3][grp][p][tid] = aprev;
    __syncthreads();
    if (tid == 0) st_release_gpu(&g_flagP[cta][0], base + 1);

    for (int t = 0; t < TT; ++t) {
        const int rb = (t + 3) & 3;
        const int wbuf = t & 3;
        const unsigned int target = base + (unsigned)t + 1;

        // prefetch xW gate values (independent of flags; DRAM latency hidden)
        const float* xwrow = &g_xw[((size_t)t * BB + bG) * G4 + hG];
        float xg0 = xwrow[0 * HH];
        float xg1 = xwrow[1 * HH];
        float xg2 = xwrow[2 * HH];
        float xg3 = xwrow[3 * HH];

        // warp 0 polls all 64 in-group producer flags (2 per lane, padded lines)
        if (w == 0) {
            wait_flag(&g_flagP[grp * 64 + lane][0], target);
            wait_flag(&g_flagP[grp * 64 + 32 + lane][0], target);
        }
        __syncthreads();

        // stream 8 slabs: a global->regs (.cg), U broadcast from smem
        ull acc[NCC];
#pragma unroll
        for (int c = 0; c < NCC; c++) acc[c] = 0ull;

        const float* abase = &g_a4[rb][grp][0][0];
        const float* s0 = abase + (w * 8) * (BPG * HPC) + lane * 8;
        float4 c0 = __ldcg((const float4*)s0);
        float4 c1 = __ldcg((const float4*)(s0 + 4));

#pragma unroll
        for (int i = 0; i < 8; i++) {
            float4 n0, n1;
            if (i < 7) {
                const float* sn = abase + (w * 8 + i + 1) * (BPG * HPC) + lane * 8;
                n0 = __ldcg((const float4*)sn);
                n1 = __ldcg((const float4*)(sn + 4));
            }
            ull av[4];
            av[0] = packf2(c0.x, c0.y);
            av[1] = packf2(c0.z, c0.w);
            av[2] = packf2(c1.x, c1.y);
            av[3] = packf2(c1.z, c1.w);
#pragma unroll
            for (int j = 0; j < 4; j++) {
                const ulonglong2* ub =
                    (const ulonglong2*)&Up[((w * 8 + i) * 4 + j) * NCC];
#pragma unroll
                for (int c = 0; c < 16; c++) {
                    ulonglong2 uv = ub[c];
                    FMA2(acc[2 * c],     av[j], uv.x, acc[2 * c]);
                    FMA2(acc[2 * c + 1], av[j], uv.y, acc[2 * c + 1]);
                }
            }
            c0 = n0; c1 = n1;
        }

        // store partials (conflict-free float4, PROW=36)
        {
            float* pr = &part[(w * 32 + lane) * PROW];
#pragma unroll
            for (int c = 0; c < NCC; c += 4) {
                float4 v;
                v.x = sum2(acc[c + 0]);
                v.y = sum2(acc[c + 1]);
                v.z = sum2(acc[c + 2]);
                v.w = sum2(acc[c + 3]);
                *(float4*)&pr[c] = v;
            }
        }
        __syncthreads();

        // reduce over 8 ksec + activations; thread = (bA, hA)
        float gsum[4];
#pragma unroll
        for (int g = 0; g < 4; g++) {
            int cc = g * 8 + hA;
            float s = 0.f;
#pragma unroll
            for (int ks = 0; ks < 8; ks++)
                s += part[(ks * 32 + bA) * PROW + cc];
            gsum[g] = s;
        }

        float gu   = sigmoidf_(gsum[0] + xg0);
        float gf   = sigmoidf_(gsum[1] + xg1);
        float go   = sigmoidf_(gsum[2] + xg2);
        float cand = tanhf(gsum[3] + xg3);
        float c_t  = gu * cand + gf * aprev;
        float a_t  = go * tanhf(c_t);
        aprev = a_t;

        // publish slab (contiguous 1KB), then flag, then output (off crit path)
        g_a4[wbuf][grp][p][tid] = a_t;
        __syncthreads();
        if (tid == 0) st_release_gpu(&g_flagP[cta][0], base + (unsigned)t + 2);

        out[((size_t)t * BB + bG) * HH + hG] = a_t;
    }
}

// ---------------- launch ------------------------------------------------------
extern "C" void kernel_launch(void* const* d_in, const int* in_sizes, int n_in,
                              void* d_out, int out_size)
{
    const float* x  = (const float*)d_in[0];
    const float* a0 = (const float*)d_in[1];
    const float* W  = (const float*)d_in[2];
    const float* U  = (const float*)d_in[3];
    const float* bb = (const float*)d_in[4];
    float* out = (float*)d_out;

    dim3 g1(G4 / 128, (TT * BB) / 128);
    xw_gemm_kernel<<<g1, 256>>>(x, W, bb);

    const int smem_bytes = 256 * NCC * 8            // Up (64KB)
                         + 8 * 32 * PROW * 4;       // partials (36KB)
    cudaFuncSetAttribute(rnn_kernel, cudaFuncAttributeMaxDynamicSharedMemorySize, smem_bytes);
    rnn_kernel<<<NCTA, 256, smem_bytes>>>(a0, U, out);
}

// round 7
// speedup vs baseline: 2.0574x; 1.1549x over previous
#include <cuda_runtime.h>
#include <math.h>

#define TT 512
#define BB 64
#define II 512
#define HH 512
#define G4 2048
#define NCTA 128
#define CPG 64          // CTAs per group
#define BPG 32          // batches per group
#define HPC 8           // h-cols per CTA
#define NCC 32          // gate-cols per CTA (4 gates x 8 h)
#define PROW 36         // padded partial row (floats)

typedef unsigned long long ull;

// ---------------- scratch ----------------------------------------------------
__device__ float g_xT[(size_t)TT * II * BB];             // x transposed: [T][I][B]
__device__ float g_a4[4][2][CPG][BPG * HPC];             // 4-deep slab ring
__device__ unsigned int g_flagP[NCTA][32];               // 128B-padded flags

// ---------------- f32x2 helpers ----------------------------------------------
#define FMA2(d, a, b, c) \
    asm("fma.rn.f32x2 %0, %1, %2, %3;" : "=l"(d) : "l"(a), "l"(b), "l"(c))

__device__ __forceinline__ ull packf2(float lo, float hi) {
    return (ull)__float_as_uint(lo) | ((ull)__float_as_uint(hi) << 32);
}
__device__ __forceinline__ float sum2(ull v) {
    return __uint_as_float((unsigned)v) + __uint_as_float((unsigned)(v >> 32));
}

__device__ __forceinline__ void st_release_gpu(unsigned int* p, unsigned int v) {
    asm volatile("st.release.gpu.global.u32 [%0], %1;" :: "l"(p), "r"(v) : "memory");
}
__device__ __forceinline__ unsigned int ld_acquire_gpu(const unsigned int* p) {
    unsigned int v;
    asm volatile("ld.acquire.gpu.global.u32 %0, [%1];" : "=r"(v) : "l"(p) : "memory");
    return v;
}
__device__ __forceinline__ void wait_flag(const unsigned int* p, unsigned int target) {
    if ((int)(ld_acquire_gpu(p) - target) >= 0) return;
    while ((int)(ld_acquire_gpu(p) - target) < 0) { __nanosleep(40); }
}

// ---------------- phase 0: transpose x -> [T][I][B] ---------------------------
__global__ void __launch_bounds__(256) transpose_x_kernel(const float* __restrict__ X)
{
    __shared__ float tile[32][33];
    const int i0 = blockIdx.x * 32;
    const int b0 = blockIdx.y * 32;
    const int t  = blockIdx.z;
    const int tx = threadIdx.x;
    const int ty = threadIdx.y;

#pragma unroll
    for (int r = 0; r < 32; r += 8)
        tile[ty + r][tx] = X[((size_t)t * BB + b0 + ty + r) * II + i0 + tx];
    __syncthreads();
#pragma unroll
    for (int r = 0; r < 32; r += 8)
        g_xT[((size_t)t * II + i0 + ty + r) * BB + b0 + tx] = tile[tx][ty + r];
}

// ---------------- fused persistent recurrence + inline x@W --------------------
__device__ __forceinline__ float sigmoidf_(float x) { return 1.0f / (1.0f + expf(-x)); }

extern __shared__ float dyn_smem[];

// smem: Up [256 kk][32 cc] ull (64KB) | Wp [256 kk][32 cc] ull (64KB)
//     | part [8 ks][32 b][PROW] float (36KB)
__global__ void __launch_bounds__(256) rnn_kernel(
    const float* __restrict__ a0,
    const float* __restrict__ U,
    const float* __restrict__ W,
    const float* __restrict__ bias,
    float* __restrict__ out)
{
    ull*   Up   = (ull*)dyn_smem;
    ull*   Wp   = Up + 256 * NCC;
    float* part = (float*)(Wp + 256 * NCC);

    const int tid  = threadIdx.x;
    const int cta  = blockIdx.x;
    const int grp  = cta >> 6;           // 0..1
    const int p    = cta & 63;           // producer index in group
    const int hc0  = p * HPC;
    const int w    = tid >> 5;           // warp = ksec 0..7
    const int lane = tid & 31;

    // activation mapping
    const int bA = tid >> 3;             // 0..31 batch in group
    const int hA = tid & 7;              // 0..7
    const int bG = grp * BPG + bA;       // global batch (activation)
    const int hG = hc0 + hA;             // global h col
    const int bL = grp * BPG + lane;     // global batch (compute lane)

    // paired slices: Up/Wp[kk*32+cc] = (M[2kk][gcol], M[2kk+1][gcol])
    for (int idx = tid; idx < 256 * NCC; idx += 256) {
        int kk = idx >> 5, cc = idx & 31;
        int gcol = (cc >> 3) * HH + hc0 + (cc & 7);
        Up[idx] = packf2(U[(size_t)(2 * kk) * G4 + gcol],
                         U[(size_t)(2 * kk + 1) * G4 + gcol]);
        Wp[idx] = packf2(W[(size_t)(2 * kk) * G4 + gcol],
                         W[(size_t)(2 * kk + 1) * G4 + gcol]);
    }

    // bias for activation phase (added once per step in the reduce)
    float bias_r[4];
#pragma unroll
    for (int g = 0; g < 4; g++) bias_r[g] = bias[g * HH + hG];

    const unsigned int base = ld_acquire_gpu(&g_flagP[cta][0]);

    // publish a_{-1} = a0 slab into ring slot 3; keep aprev in register
    float aprev = a0[(size_t)bG * HH + hG];
    g_a4[3][grp][p][tid] = aprev;
    __syncthreads();
    if (tid == 0) st_release_gpu(&g_flagP[cta][0], base + 1);

    for (int t = 0; t < TT; ++t) {
        const int rb = (t + 3) & 3;
        const int wbuf = t & 3;
        const unsigned int target = base + (unsigned)t + 1;

        ull acc[NCC];
#pragma unroll
        for (int c = 0; c < NCC; c++) acc[c] = 0ull;

        // ---- x-part: acc += x[t] @ W (no cross-CTA dependency) ----
        // warp w covers I-range [w*64, w*64+64); lane = batch bL; coalesced LDG.32
        {
            const float* xcol = &g_xT[((size_t)t * II + w * 64) * BB + bL];
            float xb[2][8];
#pragma unroll
            for (int j = 0; j < 8; j++) xb[0][j] = __ldg(&xcol[(size_t)j * BB]);

#pragma unroll
            for (int blk = 0; blk < 8; blk++) {
                const int cb = blk & 1;
                if (blk < 7) {
#pragma unroll
                    for (int j = 0; j < 8; j++)
                        xb[cb ^ 1][j] = __ldg(&xcol[(size_t)((blk + 1) * 8 + j) * BB]);
                }
#pragma unroll
                for (int jj = 0; jj < 4; jj++) {
                    ull av = packf2(xb[cb][2 * jj], xb[cb][2 * jj + 1]);
                    const ulonglong2* wb =
                        (const ulonglong2*)&Wp[(w * 32 + blk * 4 + jj) * NCC];
#pragma unroll
                    for (int c = 0; c < 16; c++) {
                        ulonglong2 uv = wb[c];
                        FMA2(acc[2 * c],     av, uv.x, acc[2 * c]);
                        FMA2(acc[2 * c + 1], av, uv.y, acc[2 * c + 1]);
                    }
                }
            }
        }

        // ---- wait for a_{t-1}: warp 0 polls all 64 in-group producer flags ----
        if (w == 0) {
            wait_flag(&g_flagP[grp * 64 + lane][0], target);
            wait_flag(&g_flagP[grp * 64 + 32 + lane][0], target);
        }
        __syncthreads();

        // ---- a-part: acc += a_{t-1} @ U (stream 8 slabs via ldcg) ----
        {
            const float* abase = &g_a4[rb][grp][0][0];
            const float* s0 = abase + (w * 8) * (BPG * HPC) + lane * 8;
            float4 c0 = __ldcg((const float4*)s0);
            float4 c1 = __ldcg((const float4*)(s0 + 4));

#pragma unroll
            for (int i = 0; i < 8; i++) {
                float4 n0, n1;
                if (i < 7) {
                    const float* sn = abase + (w * 8 + i + 1) * (BPG * HPC) + lane * 8;
                    n0 = __ldcg((const float4*)sn);
                    n1 = __ldcg((const float4*)(sn + 4));
                }
                ull av[4];
                av[0] = packf2(c0.x, c0.y);
                av[1] = packf2(c0.z, c0.w);
                av[2] = packf2(c1.x, c1.y);
                av[3] = packf2(c1.z, c1.w);
#pragma unroll
                for (int j = 0; j < 4; j++) {
                    const ulonglong2* ub =
                        (const ulonglong2*)&Up[((w * 8 + i) * 4 + j) * NCC];
#pragma unroll
                    for (int c = 0; c < 16; c++) {
                        ulonglong2 uv = ub[c];
                        FMA2(acc[2 * c],     av[j], uv.x, acc[2 * c]);
                        FMA2(acc[2 * c + 1], av[j], uv.y, acc[2 * c + 1]);
                    }
                }
                c0 = n0; c1 = n1;
            }
        }

        // ---- store partials (conflict-free float4, PROW=36) ----
        {
            float* pr = &part[(w * 32 + lane) * PROW];
#pragma unroll
            for (int c = 0; c < NCC; c += 4) {
                float4 v;
                v.x = sum2(acc[c + 0]);
                v.y = sum2(acc[c + 1]);
                v.z = sum2(acc[c + 2]);
                v.w = sum2(acc[c + 3]);
                *(float4*)&pr[c] = v;
            }
        }
        __syncthreads();

        // ---- reduce over 8 ksec + bias + activations; thread = (bA, hA) ----
        float gsum[4];
#pragma unroll
        for (int g = 0; g < 4; g++) {
            int cc = g * 8 + hA;
            float s = bias_r[g];
#pragma unroll
            for (int ks = 0; ks < 8; ks++)
                s += part[(ks * 32 + bA) * PROW + cc];
            gsum[g] = s;
        }

        float gu   = sigmoidf_(gsum[0]);
        float gf   = sigmoidf_(gsum[1]);
        float go   = sigmoidf_(gsum[2]);
        float cand = tanhf(gsum[3]);
        float c_t  = gu * cand + gf * aprev;
        float a_t  = go * tanhf(c_t);
        aprev = a_t;

        // publish slab (contiguous 1KB), then flag, then output (off crit path)
        g_a4[wbuf][grp][p][tid] = a_t;
        __syncthreads();
        if (tid == 0) st_release_gpu(&g_flagP[cta][0], base + (unsigned)t + 2);

        out[((size_t)t * BB + bG) * HH + hG] = a_t;
    }
}

// ---------------- launch ------------------------------------------------------
extern "C" void kernel_launch(void* const* d_in, const int* in_sizes, int n_in,
                              void* d_out, int out_size)
{
    const float* x  = (const float*)d_in[0];
    const float* a0 = (const float*)d_in[1];
    const float* W  = (const float*)d_in[2];
    const float* U  = (const float*)d_in[3];
    const float* bb = (const float*)d_in[4];
    float* out = (float*)d_out;

    dim3 gT(II / 32, BB / 32, TT);
    transpose_x_kernel<<<gT, dim3(32, 8)>>>(x);

    const int smem_bytes = 256 * NCC * 8 * 2        // Up + Wp (128KB)
                         + 8 * 32 * PROW * 4;       // partials (36KB)
    cudaFuncSetAttribute(rnn_kernel, cudaFuncAttributeMaxDynamicSharedMemorySize, smem_bytes);
    rnn_kernel<<<NCTA, 256, smem_bytes>>>(a0, U, W, bb, out);
}

// round 9
// speedup vs baseline: 2.1270x; 1.0338x over previous
#include <cuda_runtime.h>
#include <math.h>

#define TT 512
#define BB 64
#define II 512
#define HH 512
#define G4 2048
#define NCTA 128
#define CPG 64          // CTAs per group
#define BPG 32          // batches per group
#define HPC 8           // h-cols per CTA
#define NCC 32          // gate-cols per CTA (4 gates x 8 h)
#define PROW 36         // padded partial row (floats)
#define NW 16           // warps per CTA (= k-sections)

typedef unsigned long long ull;

// ---------------- scratch ----------------------------------------------------
__device__ float g_xT[(size_t)TT * II * BB];             // x transposed: [T][I][B]
__device__ float g_a4[4][2][CPG][BPG * HPC];             // 4-deep slab ring
__device__ unsigned int g_flagP[NCTA][32];               // 128B-padded flags

// ---------------- f32x2 helpers ----------------------------------------------
#define FMA2(d, a, b, c) \
    asm("fma.rn.f32x2 %0, %1, %2, %3;" : "=l"(d) : "l"(a), "l"(b), "l"(c))

__device__ __forceinline__ ull packf2(float lo, float hi) {
    return (ull)__float_as_uint(lo) | ((ull)__float_as_uint(hi) << 32);
}
__device__ __forceinline__ float sum2(ull v) {
    return __uint_as_float((unsigned)v) + __uint_as_float((unsigned)(v >> 32));
}

__device__ __forceinline__ void st_release_gpu(unsigned int* p, unsigned int v) {
    asm volatile("st.release.gpu.global.u32 [%0], %1;" :: "l"(p), "r"(v) : "memory");
}
__device__ __forceinline__ unsigned int ld_acquire_gpu(const unsigned int* p) {
    unsigned int v;
    asm volatile("ld.acquire.gpu.global.u32 %0, [%1];" : "=r"(v) : "l"(p) : "memory");
    return v;
}
__device__ __forceinline__ void wait_flag(const unsigned int* p, unsigned int target) {
    if ((int)(ld_acquire_gpu(p) - target) >= 0) return;
    while ((int)(ld_acquire_gpu(p) - target) < 0) { __nanosleep(40); }
}

// ---------------- phase 0: transpose x -> [T][I][B] ---------------------------
__global__ void __launch_bounds__(256) transpose_x_kernel(const float* __restrict__ X)
{
    __shared__ float tile[32][33];
    const int i0 = blockIdx.x * 32;
    const int b0 = blockIdx.y * 32;
    const int t  = blockIdx.z;
    const int tx = threadIdx.x;
    const int ty = threadIdx.y;

#pragma unroll
    for (int r = 0; r < 32; r += 8)
        tile[ty + r][tx] = X[((size_t)t * BB + b0 + ty + r) * II + i0 + tx];
    __syncthreads();
#pragma unroll
    for (int r = 0; r < 32; r += 8)
        g_xT[((size_t)t * II + i0 + ty + r) * BB + b0 + tx] = tile[tx][ty + r];
}

// ---------------- fused persistent recurrence + inline x@W --------------------
__device__ __forceinline__ float sigmoidf_(float x) { return 1.0f / (1.0f + expf(-x)); }

extern __shared__ float dyn_smem[];

// smem: Up [256 kk][32 cc] ull (64KB) | Wp [256 kk][32 cc] ull (64KB)
//     | part [16 ks][32 b][PROW] float (72KB)
__global__ void __launch_bounds__(512, 1) rnn_kernel(
    const float* __restrict__ a0,
    const float* __restrict__ U,
    const float* __restrict__ W,
    const float* __restrict__ bias,
    float* __restrict__ out)
{
    ull*   Up   = (ull*)dyn_smem;
    ull*   Wp   = Up + 256 * NCC;
    float* part = (float*)(Wp + 256 * NCC);

    const int tid  = threadIdx.x;
    const int cta  = blockIdx.x;
    const int grp  = cta >> 6;           // 0..1
    const int p    = cta & 63;           // producer index in group
    const int hc0  = p * HPC;
    const int w    = tid >> 5;           // warp = ksec 0..15 (k-range 32 each)
    const int lane = tid & 31;

    // activation mapping (threads 0..255 only)
    const int bA = (tid >> 3) & 31;      // 0..31 batch in group
    const int hA = tid & 7;              // 0..7
    const int bG = grp * BPG + bA;
    const int hG = hc0 + hA;
    const int bL = grp * BPG + lane;     // compute-lane global batch
    const bool act = (tid < 256);

    // paired slices: Up/Wp[kk*32+cc] = (M[2kk][gcol], M[2kk+1][gcol])
    for (int idx = tid; idx < 256 * NCC; idx += 512) {
        int kk = idx >> 5, cc = idx & 31;
        int gcol = (cc >> 3) * HH + hc0 + (cc & 7);
        Up[idx] = packf2(U[(size_t)(2 * kk) * G4 + gcol],
                         U[(size_t)(2 * kk + 1) * G4 + gcol]);
        Wp[idx] = packf2(W[(size_t)(2 * kk) * G4 + gcol],
                         W[(size_t)(2 * kk + 1) * G4 + gcol]);
    }

    float bias_r[4];
#pragma unroll
    for (int g = 0; g < 4; g++) bias_r[g] = bias[g * HH + hG];

    const unsigned int base = ld_acquire_gpu(&g_flagP[cta][0]);

    // publish a_{-1} = a0 slab into ring slot 3; keep aprev in register
    float aprev = 0.f;
    if (act) {
        aprev = a0[(size_t)bG * HH + hG];
        g_a4[3][grp][p][tid] = aprev;
    }
    __syncthreads();
    if (tid == 0) st_release_gpu(&g_flagP[cta][0], base + 1);

    for (int t = 0; t < TT; ++t) {
        const int rb = (t + 3) & 3;
        const int wbuf = t & 3;
        const unsigned int target = base + (unsigned)t + 1;

        ull acc[NCC];
#pragma unroll
        for (int c = 0; c < NCC; c++) acc[c] = 0ull;

        // ---- x-part: acc += x[t] @ W; warp w covers I [w*32, w*32+32) ----
        // 8 blocks of 4 I-rows, double-buffered 4-float prefetch
        {
            const float* xcol = &g_xT[((size_t)t * II + w * 32) * BB + bL];
            float xb[2][4];
#pragma unroll
            for (int j = 0; j < 4; j++) xb[0][j] = __ldg(&xcol[(size_t)j * BB]);

#pragma unroll
            for (int blk = 0; blk < 8; blk++) {
                const int cb = blk & 1;
                if (blk < 7) {
#pragma unroll
                    for (int j = 0; j < 4; j++)
                        xb[cb ^ 1][j] = __ldg(&xcol[(size_t)((blk + 1) * 4 + j) * BB]);
                }
#pragma unroll
                for (int jj = 0; jj < 2; jj++) {
                    ull av = packf2(xb[cb][2 * jj], xb[cb][2 * jj + 1]);
                    const ulonglong2* wb =
                        (const ulonglong2*)&Wp[(w * 16 + blk * 2 + jj) * NCC];
#pragma unroll
                    for (int c = 0; c < 16; c++) {
                        ulonglong2 uv = wb[c];
                        FMA2(acc[2 * c],     av, uv.x, acc[2 * c]);
                        FMA2(acc[2 * c + 1], av, uv.y, acc[2 * c + 1]);
                    }
                }
            }
        }

        // ---- wait for a_{t-1}: warp 0 polls all 64 in-group flags ----
        if (w == 0) {
            wait_flag(&g_flagP[grp * 64 + lane][0], target);
            wait_flag(&g_flagP[grp * 64 + 32 + lane][0], target);
        }
        __syncthreads();

        // ---- a-part: acc += a_{t-1} @ U; warp w streams slabs [w*4, w*4+4) ----
        {
            const float* abase = &g_a4[rb][grp][0][0];
            const float* s0 = abase + (w * 4) * (BPG * HPC) + lane * 8;
            float4 c0 = __ldcg((const float4*)s0);
            float4 c1 = __ldcg((const float4*)(s0 + 4));

#pragma unroll
            for (int i = 0; i < 4; i++) {
                float4 n0, n1;
                if (i < 3) {
                    const float* sn = abase + (w * 4 + i + 1) * (BPG * HPC) + lane * 8;
                    n0 = __ldcg((const float4*)sn);
                    n1 = __ldcg((const float4*)(sn + 4));
                }
                ull av[4];
                av[0] = packf2(c0.x, c0.y);
                av[1] = packf2(c0.z, c0.w);
                av[2] = packf2(c1.x, c1.y);
                av[3] = packf2(c1.z, c1.w);
#pragma unroll
                for (int j = 0; j < 4; j++) {
                    const ulonglong2* ub =
                        (const ulonglong2*)&Up[((w * 4 + i) * 4 + j) * NCC];
#pragma unroll
                    for (int c = 0; c < 16; c++) {
                        ulonglong2 uv = ub[c];
                        FMA2(acc[2 * c],     av[j], uv.x, acc[2 * c]);
                        FMA2(acc[2 * c + 1], av[j], uv.y, acc[2 * c + 1]);
                    }
                }
                c0 = n0; c1 = n1;
            }
        }

        // ---- store partials (conflict-free float4, PROW=36) ----
        {
            float* pr = &part[(w * 32 + lane) * PROW];
#pragma unroll
            for (int c = 0; c < NCC; c += 4) {
                float4 v;
                v.x = sum2(acc[c + 0]);
                v.y = sum2(acc[c + 1]);
                v.z = sum2(acc[c + 2]);
                v.w = sum2(acc[c + 3]);
                *(float4*)&pr[c] = v;
            }
        }
        __syncthreads();

        // ---- reduce over 16 ksec + bias + activations (threads 0..255) ----
        float a_t = 0.f;
        if (act) {
            float gsum[4];
#pragma unroll
            for (int g = 0; g < 4; g++) {
                int cc = g * 8 + hA;
                float s = bias_r[g];
#pragma unroll
                for (int ks = 0; ks < NW; ks++)
                    s += part[(ks * 32 + bA) * PROW + cc];
                gsum[g] = s;
            }

            float gu   = sigmoidf_(gsum[0]);
            float gf   = sigmoidf_(gsum[1]);
            float go   = sigmoidf_(gsum[2]);
            float cand = tanhf(gsum[3]);
            float c_t  = gu * cand + gf * aprev;
            a_t = go * tanhf(c_t);
            aprev = a_t;

            g_a4[wbuf][grp][p][tid] = a_t;
        }
        __syncthreads();
        if (tid == 0) st_release_gpu(&g_flagP[cta][0], base + (unsigned)t + 2);

        if (act) out[((size_t)t * BB + bG) * HH + hG] = a_t;
    }
}

// ---------------- launch ------------------------------------------------------
extern "C" void kernel_launch(void* const* d_in, const int* in_sizes, int n_in,
                              void* d_out, int out_size)
{
    const float* x  = (const float*)d_in[0];
    const float* a0 = (const float*)d_in[1];
    const float* W  = (const float*)d_in[2];
    const float* U  = (const float*)d_in[3];
    const float* bb = (const float*)d_in[4];
    float* out = (float*)d_out;

    dim3 gT(II / 32, BB / 32, TT);
    transpose_x_kernel<<<gT, dim3(32, 8)>>>(x);

    const int smem_bytes = 256 * NCC * 8 * 2        // Up + Wp (128KB)
                         + NW * 32 * PROW * 4;      // partials (72KB)
    cudaFuncSetAttribute(rnn_kernel, cudaFuncAttributeMaxDynamicSharedMemorySize, smem_bytes);
    rnn_kernel<<<NCTA, 512, smem_bytes>>>(a0, U, W, bb, out);
}